// round 16
// baseline (speedup 1.0000x reference)
#include <cuda_runtime.h>
#include <cuda_fp16.h>
#include <cstdint>
#include <cstddef>

#define B_  64
#define T_  1024
#define F_  512
#define H_  512
#define G4_ 2048   // 4H
#define NCTA 128
#define GCTA 8192

__device__ float  g_xproj[(size_t)T_ * B_ * G4_];        // [t][b][col] fp32
__device__ __half g_hbufh[2][H_ * B_];                   // [col(k)][b] fp16, double-buffered
__device__ unsigned g_flags[NCTA * 32];                  // lstm flags, 1 per 128B line
__device__ unsigned g_slab[8 * 32];                      // per-slab done counters, 128B apart
__device__ __half g_ah[(size_t)B_ * T_ * F_];            // inputs as fp16 [m][k]
__device__ __half g_bh[(size_t)G4_ * F_];                // Wx^T fp16 [n][k]

// ---------------------------------------------------------------------------
// helpers
// ---------------------------------------------------------------------------
__device__ __forceinline__ void cp16(void* dst, const void* src)
{
    unsigned d = (unsigned)__cvta_generic_to_shared(dst);
    asm volatile("cp.async.cg.shared.global [%0], [%1], 16;" :: "r"(d), "l"(src) : "memory");
}

__device__ __forceinline__ unsigned ld_acq(const unsigned* p)
{
    unsigned v;
    asm volatile("ld.acquire.gpu.global.u32 %0, [%1];" : "=r"(v) : "l"(p) : "memory");
    return v;
}

__device__ __forceinline__ void st_rel(unsigned* p, unsigned v)
{
    asm volatile("st.release.gpu.global.u32 [%0], %1;" :: "l"(p), "r"(v) : "memory");
}

__device__ __forceinline__ unsigned pack2(float a, float b)
{
    __half2 h = __floats2half2_rn(a, b);
    return *(unsigned*)&h;
}

__device__ __forceinline__ void mma16(float* c,
    unsigned a0, unsigned a1, unsigned a2, unsigned a3,
    unsigned b0, unsigned b1)
{
    asm volatile(
        "mma.sync.aligned.m16n8k16.row.col.f32.f16.f16.f32 "
        "{%0,%1,%2,%3}, {%4,%5,%6,%7}, {%8,%9}, {%0,%1,%2,%3};"
        : "+f"(c[0]), "+f"(c[1]), "+f"(c[2]), "+f"(c[3])
        : "r"(a0), "r"(a1), "r"(a2), "r"(a3), "r"(b0), "r"(b1));
}

__device__ __forceinline__ void ldmx4(unsigned* r, unsigned addr)
{
    asm volatile(
        "ldmatrix.sync.aligned.m8n8.x4.shared.b16 {%0,%1,%2,%3}, [%4];"
        : "=r"(r[0]), "=r"(r[1]), "=r"(r[2]), "=r"(r[3]) : "r"(addr));
}

__device__ __forceinline__ void ldmx4t(unsigned* r, unsigned addr)
{
    asm volatile(
        "ldmatrix.sync.aligned.m8n8.x4.trans.shared.b16 {%0,%1,%2,%3}, [%4];"
        : "=r"(r[0]), "=r"(r[1]), "=r"(r[2]), "=r"(r[3]) : "r"(addr));
}

__device__ __forceinline__ uint32_t smem_to_u32(const void* p) {
    uint32_t a;
    asm("{ .reg .u64 t; cvta.to.shared.u64 t, %1; cvt.u32.u64 %0, t; }"
        : "=r"(a) : "l"(p));
    return a;
}

// ---------------------------------------------------------------------------
// Prep kernels: inputs -> fp16 [m][k]; Wx -> transposed fp16 [n][k]
// ---------------------------------------------------------------------------
__global__ void __launch_bounds__(256) conv_a(const float* __restrict__ A)
{
    unsigned i0 = blockIdx.x * 256 + threadIdx.x;
#pragma unroll
    for (int j = 0; j < 8; j++) {
        unsigned i = i0 + j * (8192u * 256u);
        float2 v = ((const float2*)A)[i];
        ((unsigned*)g_ah)[i] = pack2(v.x, v.y);
    }
}

__global__ void __launch_bounds__(256) conv_b(const float* __restrict__ W)
{
    unsigned i = blockIdx.x * 256 + threadIdx.x;
    int k = i >> 11, n = i & 2047;
    g_bh[(size_t)n * 512 + k] = __float2half_rn(W[i]);
}

// ---------------------------------------------------------------------------
// Fused heterogeneous kernel:
//   blockIdx <  128 : persistent LSTM CTA (R15 datapath; x_proj via register
//                     prefetch + per-slab readiness polls; no sx smem)
//   blockIdx >= 128 : one GEMM tile CTA (R10 gemm_f16 body), slab-major order
//                     (slab s = t in [128s,128s+128) = contiguous 1024 CTAs),
//                     release-counts into g_slab[s] on completion.
// Occupancy 2 engineered: smem 110592 B/CTA (x2 = 221184 <= 228KB), regs<=128
// via launch_bounds(256,2) -> every SM holds its LSTM CTA + a GEMM CTA slot.
// ---------------------------------------------------------------------------
#define GROW 80
#define GTILE (128 * GROW)
#define GSTAGE (2 * GTILE)

#define SHH_STRIDE 72
#define SHH_CHUNK (128 * SHH_STRIDE)
#define SG_STRIDE 18
#define SG_WARP  (64 * SG_STRIDE)
#define FSMEM (4 * SHH_CHUNK * 2 + 8 * SG_WARP * 4)   // 110592 B

__global__ void __launch_bounds__(256, 2) fused_kernel(
    const float* __restrict__ Wh,
    const float* __restrict__ bias,
    float* __restrict__ out)
{
    extern __shared__ char smraw[];
    const int tid = threadIdx.x;
    const int warp = tid >> 5, lane = tid & 31;
    const int r = lane >> 2, cq = lane & 3;

    if (blockIdx.x >= NCTA) {
        // ================= GEMM path =================
        const int g    = blockIdx.x - NCTA;
        const int slab = g >> 10;
        const int q    = g & 1023;
        const int m0   = (((q >> 4) << 3) + slab) * 128;   // b*1024 + slab*128 rows
        const int n0   = (q & 15) * 128;

        const unsigned sm32 = smem_to_u32(smraw);
        const int wm = warp & 1, wn = warp >> 1;
        const int lr = lane & 15, lh = lane >> 4;

        float* sbias = (float*)smraw;
        if (tid < 128) sbias[tid] = bias[n0 + tid];

        float acc[4][4][4];
#pragma unroll
        for (int i = 0; i < 4; i++)
#pragma unroll
            for (int j = 0; j < 4; j++)
#pragma unroll
                for (int k = 0; k < 4; k++) acc[i][j][k] = 0.f;

        auto issue = [&](int s) {
            char* base = smraw + 1024 + (s & 3) * GSTAGE;
#pragma unroll
            for (int i = 0; i < 4; i++) {
                int idx  = tid + i * 256;
                int tile = idx >> 9;
                int qq   = idx & 511;
                int row  = qq >> 2, seg = qq & 3;
                const __half* src =
                    (tile == 0) ? g_ah + (size_t)(m0 + row) * 512 + s * 32 + seg * 8 :
                                  g_bh + (size_t)(n0 + row) * 512 + s * 32 + seg * 8;
                cp16(base + tile * GTILE + row * GROW + seg * 16, src);
            }
            asm volatile("cp.async.commit_group;" ::: "memory");
        };

        issue(0);
        issue(1);
        issue(2);

        for (int s = 0; s < 16; s++) {
            if (s <= 13)      { asm volatile("cp.async.wait_group 2;" ::: "memory"); }
            else if (s == 14) { asm volatile("cp.async.wait_group 1;" ::: "memory"); }
            else              { asm volatile("cp.async.wait_group 0;" ::: "memory"); }
            __syncthreads();
            if (s + 3 < 16) issue(s + 3);

            const unsigned sb = sm32 + 1024 + (s & 3) * GSTAGE;
            const unsigned Aad = sb + (wm * 64 + lr) * GROW + lh * 16;
            const unsigned Bad = sb + GTILE + (wn * 32 + lr) * GROW + lh * 16;

#pragma unroll
            for (int kk = 0; kk < 2; kk++) {
                unsigned a[4][4];
#pragma unroll
                for (int mt = 0; mt < 4; mt++)
                    ldmx4(a[mt], Aad + mt * 16 * GROW + kk * 32);

#pragma unroll
                for (int p = 0; p < 2; p++) {
                    unsigned bq[4];
                    ldmx4(bq, Bad + p * 16 * GROW + kk * 32);
#pragma unroll
                    for (int mt = 0; mt < 4; mt++) {
                        mma16(acc[mt][2 * p],     a[mt][0], a[mt][1], a[mt][2], a[mt][3], bq[0], bq[2]);
                        mma16(acc[mt][2 * p + 1], a[mt][0], a[mt][1], a[mt][2], a[mt][3], bq[1], bq[3]);
                    }
                }
            }
        }

        const int mbase = m0 + wm * 64;
        const int nbase = n0 + wn * 32;
#pragma unroll
        for (int nt = 0; nt < 4; nt++) {
            int nn = nbase + nt * 8 + cq * 2;
            float2 bb = *(const float2*)(sbias + nt * 8 + cq * 2 + wn * 32);
#pragma unroll
            for (int mt = 0; mt < 4; mt++) {
                int row0 = mbase + mt * 16 + r;
                int t0 = row0 & (T_ - 1), bi0 = row0 >> 10;
                float2 v0 = make_float2(acc[mt][nt][0] + bb.x, acc[mt][nt][1] + bb.y);
                *(float2*)&g_xproj[((size_t)(t0 * 64 + bi0) << 11) + nn] = v0;
                int row1 = row0 + 8;
                int t1 = row1 & (T_ - 1), bi1 = row1 >> 10;
                float2 v1 = make_float2(acc[mt][nt][2] + bb.x, acc[mt][nt][3] + bb.y);
                *(float2*)&g_xproj[((size_t)(t1 * 64 + bi1) << 11) + nn] = v1;
            }
        }

        __threadfence();           // order xproj stores before the count
        __syncthreads();
        if (tid == 0) atomicAdd(&g_slab[slab * 32], 1u);
        return;
    }

    // ================= LSTM path =================
    __half* sh = (__half*)smraw;                              // 4*9216 halves
    float*  sg = (float*)(smraw + 4 * SHH_CHUNK * 2);         // 8*64*18 floats

    const unsigned sh32 = smem_to_u32(sh);
    const int cta = blockIdx.x;

    const unsigned base = ld_acq(&g_flags[cta * 32]);
    // replay index R = base/1025 (flags advance exactly 1025/launch);
    // slab counters advance exactly 1024/launch -> target below.
    const unsigned slabtgt = (base / 1025u + 1u) * 1024u;

    // Preload Wh fragments as fp16 half2 (single term). Warp owns k16-tile
    // k0 = c*128 + warp*16 of each chunk c.
    unsigned BH[4][2][2];
#pragma unroll
    for (int c = 0; c < 4; c++) {
        int k0 = c * 128 + warp * 16;
#pragma unroll
        for (int nt = 0; nt < 2; nt++) {
            int n = nt * 8 + r;
            int col = ((n >> 2) << 9) + (cta << 2) + (n & 3);
            float w00 = Wh[(size_t)(k0 + 2 * cq)     * G4_ + col];
            float w01 = Wh[(size_t)(k0 + 2 * cq + 1) * G4_ + col];
            float w10 = Wh[(size_t)(k0 + 2 * cq + 8) * G4_ + col];
            float w11 = Wh[(size_t)(k0 + 2 * cq + 9) * G4_ + col];
            BH[c][nt][0] = pack2(w00, w01);
            BH[c][nt][1] = pack2(w10, w11);
        }
    }

    // zero h buffer 0
    if (tid < 128) ((unsigned*)g_hbufh[0])[cta * 128 + tid] = 0u;

    __syncthreads();
    {   // barrier 0: init complete across the 128 LSTM CTAs
        unsigned tgt = base + 1;
        if (tid == 0) st_rel(&g_flags[cta * 32], tgt);
        if (tid < NCTA)
            while ((int)(ld_acq(&g_flags[tid * 32]) - tgt) < 0) {}
        __syncthreads();
    }

    const int eb = tid >> 2, ej = tid & 3;
    const int colj = (cta << 2) + ej;
    float c_reg = 0.f;

    // wait for x_proj slab 0, then load x(0) into registers
    while ((int)(ld_acq(&g_slab[0]) - slabtgt) < 0) {}
    float xcur[4];
#pragma unroll
    for (int gg = 0; gg < 4; gg++)
        xcur[gg] = g_xproj[((size_t)eb << 11) + ((size_t)gg << 9) + (cta << 2) + ej];

    const int klrow = (lane & 7) + ((lane >> 4) << 3);
    const int bcol8 = lane & 8;

    auto issue_chunk = [&](const __half* hsrc, int ch) {
        const __half* s0 = hsrc + (size_t)(ch * 128 + warp * 16) * 64;
        __half* d0 = sh + ch * SHH_CHUNK + (warp * 16) * SHH_STRIDE;
#pragma unroll
        for (int i = 0; i < 4; i++) {
            int s_ = lane + 32 * i;
            int row = s_ >> 3, seg = s_ & 7;
            cp16(d0 + row * SHH_STRIDE + seg * 8, s0 + row * 64 + seg * 8);
        }
        asm volatile("cp.async.commit_group;" ::: "memory");
    };

    for (int t = 0; t < T_; t++) {
        const __half* hsrc = g_hbufh[t & 1];

        // slab-boundary readiness poll for x(t+1), then register prefetch
        if ((t + 1) < T_ && (((t + 1) & 127) == 0)) {
            const unsigned* sc = &g_slab[((t + 1) >> 7) << 5];
            while ((int)(ld_acq(sc) - slabtgt) < 0) {}
        }
        float xnext[4] = {0.f, 0.f, 0.f, 0.f};
        if (t + 1 < T_) {
#pragma unroll
            for (int gg = 0; gg < 4; gg++)
                xnext[gg] = g_xproj[((size_t)((t + 1) * 64 + eb) << 11)
                                    + ((size_t)gg << 9) + (cta << 2) + ej];
        }

        issue_chunk(hsrc, 0);
        issue_chunk(hsrc, 1);
        issue_chunk(hsrc, 2);
        issue_chunk(hsrc, 3);

        float acc[4][2][4];
#pragma unroll
        for (int mt = 0; mt < 4; mt++)
#pragma unroll
            for (int nt = 0; nt < 2; nt++)
#pragma unroll
                for (int k = 0; k < 4; k++) acc[mt][nt][k] = 0.f;

#pragma unroll
        for (int ch = 0; ch < 4; ch++) {
            switch (ch) {
                case 0: asm volatile("cp.async.wait_group 3;" ::: "memory"); break;
                case 1: asm volatile("cp.async.wait_group 2;" ::: "memory"); break;
                case 2: asm volatile("cp.async.wait_group 1;" ::: "memory"); break;
                default: asm volatile("cp.async.wait_group 0;" ::: "memory"); break;
            }
            __syncwarp();

            const unsigned hb32 = sh32 +
                ((unsigned)(ch * SHH_CHUNK + (warp * 16 + klrow) * SHH_STRIDE + bcol8) << 1);

            unsigned a[4][4];
#pragma unroll
            for (int mt = 0; mt < 4; mt++)
                ldmx4t(a[mt], hb32 + (mt * 16 << 1));

#pragma unroll
            for (int nt = 0; nt < 2; nt++)
#pragma unroll
                for (int mt = 0; mt < 4; mt++)
                    mma16(acc[mt][nt], a[mt][0], a[mt][1], a[mt][2], a[mt][3],
                          BH[ch][nt][0], BH[ch][nt][1]);
        }

        {
            float* sgp = sg + warp * SG_WARP;
#pragma unroll
            for (int mt = 0; mt < 4; mt++) {
                int b0 = mt * 16 + r;
#pragma unroll
                for (int nt = 0; nt < 2; nt++) {
                    int n = nt * 8 + cq * 2;
                    *(float2*)&sgp[b0 * SG_STRIDE + n] =
                        make_float2(acc[mt][nt][0], acc[mt][nt][1]);
                    *(float2*)&sgp[(b0 + 8) * SG_STRIDE + n] =
                        make_float2(acc[mt][nt][2], acc[mt][nt][3]);
                }
            }
        }
        __syncthreads();

        {
            float v[4];
#pragma unroll
            for (int g = 0; g < 4; g++) {
                int n = (g << 2) + ej;
                float s = xcur[g];
#pragma unroll
                for (int w = 0; w < 8; w++) s += sg[w * SG_WARP + eb * SG_STRIDE + n];
                v[g] = s;
            }
            float si = 1.f / (1.f + __expf(-v[0]));
            float sf = 1.f / (1.f + __expf(-v[1]));
            float tg = tanhf(v[2]);
            float so = 1.f / (1.f + __expf(-v[3]));
            c_reg = sf * c_reg + si * tg;
            float hn = so * tanhf(c_reg);

            g_hbufh[(t + 1) & 1][(colj << 6) + eb] = __float2half_rn(hn);

            if (t == T_ - 1) {
                out[eb * H_ + colj]           = c_reg;   // c_fin
                out[B_ * H_ + eb * H_ + colj] = hn;      // h_fin
            }
        }

#pragma unroll
        for (int gg = 0; gg < 4; gg++) xcur[gg] = xnext[gg];

        __syncthreads();
        {
            unsigned tgt = base + 2 + (unsigned)t;
            if (tid == 0) st_rel(&g_flags[cta * 32], tgt);
            if (tid < NCTA)
                while ((int)(ld_acq(&g_flags[tid * 32]) - tgt) < 0) {}
            __syncthreads();
        }
    }
}

// ---------------------------------------------------------------------------
extern "C" void kernel_launch(void* const* d_in, const int* in_sizes, int n_in,
                              void* d_out, int out_size)
{
    const float* inputs = (const float*)d_in[0];  // [B, T, F]
    const float* Wx     = (const float*)d_in[1];  // [F, 4H]
    const float* Wh     = (const float*)d_in[2];  // [H, 4H]
    const float* bias   = (const float*)d_in[3];  // [4H]
    float* out = (float*)d_out;                   // [2, B, H] = (c_fin, h_fin)

    (void)in_sizes; (void)n_in; (void)out_size;

    conv_a<<<8192, 256>>>(inputs);
    conv_b<<<4096, 256>>>(Wx);

    cudaFuncSetAttribute(fused_kernel, cudaFuncAttributeMaxDynamicSharedMemorySize, FSMEM);
    fused_kernel<<<NCTA + GCTA, 256, FSMEM>>>(Wh, bias, out);
}

// round 17
// speedup vs baseline: 1.0220x; 1.0220x over previous
#include <cuda_runtime.h>
#include <cuda_fp16.h>
#include <cstdint>
#include <cstddef>

#define B_  64
#define T_  1024
#define F_  512
#define H_  512
#define G4_ 2048   // 4H
#define NCTA 128
#define GCTA 8192

__device__ float  g_xproj[(size_t)T_ * B_ * G4_];        // [t][b][col] fp32
__device__ __half g_hbufh[2][H_ * B_];                   // [col(k)][b] fp16, double-buffered
__device__ unsigned g_flags[NCTA * 32];                  // lstm flags, 1 per 128B line
__device__ unsigned g_slab[8 * 32];                      // per-slab done counters, 128B apart
__device__ __half g_ah[(size_t)B_ * T_ * F_];            // inputs as fp16 [m][k]
__device__ __half g_bh[(size_t)G4_ * F_];                // Wx^T fp16 [n][k]

// ---------------------------------------------------------------------------
// helpers
// ---------------------------------------------------------------------------
__device__ __forceinline__ void cp16(void* dst, const void* src)
{
    unsigned d = (unsigned)__cvta_generic_to_shared(dst);
    asm volatile("cp.async.cg.shared.global [%0], [%1], 16;" :: "r"(d), "l"(src) : "memory");
}

__device__ __forceinline__ unsigned ld_acq(const unsigned* p)
{
    unsigned v;
    asm volatile("ld.acquire.gpu.global.u32 %0, [%1];" : "=r"(v) : "l"(p) : "memory");
    return v;
}

__device__ __forceinline__ void st_rel(unsigned* p, unsigned v)
{
    asm volatile("st.release.gpu.global.u32 [%0], %1;" :: "l"(p), "r"(v) : "memory");
}

// streaming (evict-first) store: keep x_proj out of L2 working set
__device__ __forceinline__ void st_cs2(float* p, float a, float b)
{
    asm volatile("st.global.cs.v2.f32 [%0], {%1, %2};" :: "l"(p), "f"(a), "f"(b) : "memory");
}

__device__ __forceinline__ unsigned pack2(float a, float b)
{
    __half2 h = __floats2half2_rn(a, b);
    return *(unsigned*)&h;
}

__device__ __forceinline__ void mma16(float* c,
    unsigned a0, unsigned a1, unsigned a2, unsigned a3,
    unsigned b0, unsigned b1)
{
    asm volatile(
        "mma.sync.aligned.m16n8k16.row.col.f32.f16.f16.f32 "
        "{%0,%1,%2,%3}, {%4,%5,%6,%7}, {%8,%9}, {%0,%1,%2,%3};"
        : "+f"(c[0]), "+f"(c[1]), "+f"(c[2]), "+f"(c[3])
        : "r"(a0), "r"(a1), "r"(a2), "r"(a3), "r"(b0), "r"(b1));
}

__device__ __forceinline__ void ldmx4(unsigned* r, unsigned addr)
{
    asm volatile(
        "ldmatrix.sync.aligned.m8n8.x4.shared.b16 {%0,%1,%2,%3}, [%4];"
        : "=r"(r[0]), "=r"(r[1]), "=r"(r[2]), "=r"(r[3]) : "r"(addr));
}

__device__ __forceinline__ void ldmx4t(unsigned* r, unsigned addr)
{
    asm volatile(
        "ldmatrix.sync.aligned.m8n8.x4.trans.shared.b16 {%0,%1,%2,%3}, [%4];"
        : "=r"(r[0]), "=r"(r[1]), "=r"(r[2]), "=r"(r[3]) : "r"(addr));
}

__device__ __forceinline__ uint32_t smem_to_u32(const void* p) {
    uint32_t a;
    asm("{ .reg .u64 t; cvta.to.shared.u64 t, %1; cvt.u32.u64 %0, t; }"
        : "=r"(a) : "l"(p));
    return a;
}

// ---------------------------------------------------------------------------
// Prep kernels: inputs -> fp16 [m][k]; Wx -> transposed fp16 [n][k]
// ---------------------------------------------------------------------------
__global__ void __launch_bounds__(256) conv_a(const float* __restrict__ A)
{
    unsigned i0 = blockIdx.x * 256 + threadIdx.x;
#pragma unroll
    for (int j = 0; j < 8; j++) {
        unsigned i = i0 + j * (8192u * 256u);
        float2 v = ((const float2*)A)[i];
        ((unsigned*)g_ah)[i] = pack2(v.x, v.y);
    }
}

__global__ void __launch_bounds__(256) conv_b(const float* __restrict__ W)
{
    unsigned i = blockIdx.x * 256 + threadIdx.x;
    int k = i >> 11, n = i & 2047;
    g_bh[(size_t)n * 512 + k] = __float2half_rn(W[i]);
}

// ---------------------------------------------------------------------------
// Fused heterogeneous kernel (R16 structure):
//   blockIdx <  128 : persistent LSTM CTA
//   blockIdx >= 128 : one GEMM tile CTA, slab-major, counts into g_slab[s].
// ONLY change vs R16: GEMM epilogue uses st.global.cs (evict-first) so the
// 512MB x_proj stream does not evict the LSTM's h/flag lines from L2.
// ---------------------------------------------------------------------------
#define GROW 80
#define GTILE (128 * GROW)
#define GSTAGE (2 * GTILE)

#define SHH_STRIDE 72
#define SHH_CHUNK (128 * SHH_STRIDE)
#define SG_STRIDE 18
#define SG_WARP  (64 * SG_STRIDE)
#define FSMEM (4 * SHH_CHUNK * 2 + 8 * SG_WARP * 4)   // 110592 B

__global__ void __launch_bounds__(256, 2) fused_kernel(
    const float* __restrict__ Wh,
    const float* __restrict__ bias,
    float* __restrict__ out)
{
    extern __shared__ char smraw[];
    const int tid = threadIdx.x;
    const int warp = tid >> 5, lane = tid & 31;
    const int r = lane >> 2, cq = lane & 3;

    if (blockIdx.x >= NCTA) {
        // ================= GEMM path =================
        const int g    = blockIdx.x - NCTA;
        const int slab = g >> 10;
        const int q    = g & 1023;
        const int m0   = (((q >> 4) << 3) + slab) * 128;   // b*1024 + slab*128 rows
        const int n0   = (q & 15) * 128;

        const unsigned sm32 = smem_to_u32(smraw);
        const int wm = warp & 1, wn = warp >> 1;
        const int lr = lane & 15, lh = lane >> 4;

        float* sbias = (float*)smraw;
        if (tid < 128) sbias[tid] = bias[n0 + tid];

        float acc[4][4][4];
#pragma unroll
        for (int i = 0; i < 4; i++)
#pragma unroll
            for (int j = 0; j < 4; j++)
#pragma unroll
                for (int k = 0; k < 4; k++) acc[i][j][k] = 0.f;

        auto issue = [&](int s) {
            char* base = smraw + 1024 + (s & 3) * GSTAGE;
#pragma unroll
            for (int i = 0; i < 4; i++) {
                int idx  = tid + i * 256;
                int tile = idx >> 9;
                int qq   = idx & 511;
                int row  = qq >> 2, seg = qq & 3;
                const __half* src =
                    (tile == 0) ? g_ah + (size_t)(m0 + row) * 512 + s * 32 + seg * 8 :
                                  g_bh + (size_t)(n0 + row) * 512 + s * 32 + seg * 8;
                cp16(base + tile * GTILE + row * GROW + seg * 16, src);
            }
            asm volatile("cp.async.commit_group;" ::: "memory");
        };

        issue(0);
        issue(1);
        issue(2);

        for (int s = 0; s < 16; s++) {
            if (s <= 13)      { asm volatile("cp.async.wait_group 2;" ::: "memory"); }
            else if (s == 14) { asm volatile("cp.async.wait_group 1;" ::: "memory"); }
            else              { asm volatile("cp.async.wait_group 0;" ::: "memory"); }
            __syncthreads();
            if (s + 3 < 16) issue(s + 3);

            const unsigned sb = sm32 + 1024 + (s & 3) * GSTAGE;
            const unsigned Aad = sb + (wm * 64 + lr) * GROW + lh * 16;
            const unsigned Bad = sb + GTILE + (wn * 32 + lr) * GROW + lh * 16;

#pragma unroll
            for (int kk = 0; kk < 2; kk++) {
                unsigned a[4][4];
#pragma unroll
                for (int mt = 0; mt < 4; mt++)
                    ldmx4(a[mt], Aad + mt * 16 * GROW + kk * 32);

#pragma unroll
                for (int p = 0; p < 2; p++) {
                    unsigned bq[4];
                    ldmx4(bq, Bad + p * 16 * GROW + kk * 32);
#pragma unroll
                    for (int mt = 0; mt < 4; mt++) {
                        mma16(acc[mt][2 * p],     a[mt][0], a[mt][1], a[mt][2], a[mt][3], bq[0], bq[2]);
                        mma16(acc[mt][2 * p + 1], a[mt][0], a[mt][1], a[mt][2], a[mt][3], bq[1], bq[3]);
                    }
                }
            }
        }

        const int mbase = m0 + wm * 64;
        const int nbase = n0 + wn * 32;
#pragma unroll
        for (int nt = 0; nt < 4; nt++) {
            int nn = nbase + nt * 8 + cq * 2;
            float2 bb = *(const float2*)(sbias + nt * 8 + cq * 2 + wn * 32);
#pragma unroll
            for (int mt = 0; mt < 4; mt++) {
                int row0 = mbase + mt * 16 + r;
                int t0 = row0 & (T_ - 1), bi0 = row0 >> 10;
                st_cs2(&g_xproj[((size_t)(t0 * 64 + bi0) << 11) + nn],
                       acc[mt][nt][0] + bb.x, acc[mt][nt][1] + bb.y);
                int row1 = row0 + 8;
                int t1 = row1 & (T_ - 1), bi1 = row1 >> 10;
                st_cs2(&g_xproj[((size_t)(t1 * 64 + bi1) << 11) + nn],
                       acc[mt][nt][2] + bb.x, acc[mt][nt][3] + bb.y);
            }
        }

        __threadfence();           // order xproj stores before the count
        __syncthreads();
        if (tid == 0) atomicAdd(&g_slab[slab * 32], 1u);
        return;
    }

    // ================= LSTM path =================
    __half* sh = (__half*)smraw;                              // 4*9216 halves
    float*  sg = (float*)(smraw + 4 * SHH_CHUNK * 2);         // 8*64*18 floats

    const unsigned sh32 = smem_to_u32(sh);
    const int cta = blockIdx.x;

    const unsigned base = ld_acq(&g_flags[cta * 32]);
    // replay index R = base/1025 (flags advance exactly 1025/launch);
    // slab counters advance exactly 1024/launch -> target below.
    const unsigned slabtgt = (base / 1025u + 1u) * 1024u;

    // Preload Wh fragments as fp16 half2 (single term). Warp owns k16-tile
    // k0 = c*128 + warp*16 of each chunk c.
    unsigned BH[4][2][2];
#pragma unroll
    for (int c = 0; c < 4; c++) {
        int k0 = c * 128 + warp * 16;
#pragma unroll
        for (int nt = 0; nt < 2; nt++) {
            int n = nt * 8 + r;
            int col = ((n >> 2) << 9) + (cta << 2) + (n & 3);
            float w00 = Wh[(size_t)(k0 + 2 * cq)     * G4_ + col];
            float w01 = Wh[(size_t)(k0 + 2 * cq + 1) * G4_ + col];
            float w10 = Wh[(size_t)(k0 + 2 * cq + 8) * G4_ + col];
            float w11 = Wh[(size_t)(k0 + 2 * cq + 9) * G4_ + col];
            BH[c][nt][0] = pack2(w00, w01);
            BH[c][nt][1] = pack2(w10, w11);
        }
    }

    // zero h buffer 0
    if (tid < 128) ((unsigned*)g_hbufh[0])[cta * 128 + tid] = 0u;

    __syncthreads();
    {   // barrier 0: init complete across the 128 LSTM CTAs
        unsigned tgt = base + 1;
        if (tid == 0) st_rel(&g_flags[cta * 32], tgt);
        if (tid < NCTA)
            while ((int)(ld_acq(&g_flags[tid * 32]) - tgt) < 0) {}
        __syncthreads();
    }

    const int eb = tid >> 2, ej = tid & 3;
    const int colj = (cta << 2) + ej;
    float c_reg = 0.f;

    // wait for x_proj slab 0, then load x(0) into registers
    while ((int)(ld_acq(&g_slab[0]) - slabtgt) < 0) {}
    float xcur[4];
#pragma unroll
    for (int gg = 0; gg < 4; gg++)
        xcur[gg] = g_xproj[((size_t)eb << 11) + ((size_t)gg << 9) + (cta << 2) + ej];

    const int klrow = (lane & 7) + ((lane >> 4) << 3);
    const int bcol8 = lane & 8;

    auto issue_chunk = [&](const __half* hsrc, int ch) {
        const __half* s0 = hsrc + (size_t)(ch * 128 + warp * 16) * 64;
        __half* d0 = sh + ch * SHH_CHUNK + (warp * 16) * SHH_STRIDE;
#pragma unroll
        for (int i = 0; i < 4; i++) {
            int s_ = lane + 32 * i;
            int row = s_ >> 3, seg = s_ & 7;
            cp16(d0 + row * SHH_STRIDE + seg * 8, s0 + row * 64 + seg * 8);
        }
        asm volatile("cp.async.commit_group;" ::: "memory");
    };

    for (int t = 0; t < T_; t++) {
        const __half* hsrc = g_hbufh[t & 1];

        // slab-boundary readiness poll for x(t+1), then register prefetch
        if ((t + 1) < T_ && (((t + 1) & 127) == 0)) {
            const unsigned* sc = &g_slab[((t + 1) >> 7) << 5];
            while ((int)(ld_acq(sc) - slabtgt) < 0) {}
        }
        float xnext[4] = {0.f, 0.f, 0.f, 0.f};
        if (t + 1 < T_) {
#pragma unroll
            for (int gg = 0; gg < 4; gg++)
                xnext[gg] = g_xproj[((size_t)((t + 1) * 64 + eb) << 11)
                                    + ((size_t)gg << 9) + (cta << 2) + ej];
        }

        issue_chunk(hsrc, 0);
        issue_chunk(hsrc, 1);
        issue_chunk(hsrc, 2);
        issue_chunk(hsrc, 3);

        float acc[4][2][4];
#pragma unroll
        for (int mt = 0; mt < 4; mt++)
#pragma unroll
            for (int nt = 0; nt < 2; nt++)
#pragma unroll
                for (int k = 0; k < 4; k++) acc[mt][nt][k] = 0.f;

#pragma unroll
        for (int ch = 0; ch < 4; ch++) {
            switch (ch) {
                case 0: asm volatile("cp.async.wait_group 3;" ::: "memory"); break;
                case 1: asm volatile("cp.async.wait_group 2;" ::: "memory"); break;
                case 2: asm volatile("cp.async.wait_group 1;" ::: "memory"); break;
                default: asm volatile("cp.async.wait_group 0;" ::: "memory"); break;
            }
            __syncwarp();

            const unsigned hb32 = sh32 +
                ((unsigned)(ch * SHH_CHUNK + (warp * 16 + klrow) * SHH_STRIDE + bcol8) << 1);

            unsigned a[4][4];
#pragma unroll
            for (int mt = 0; mt < 4; mt++)
                ldmx4t(a[mt], hb32 + (mt * 16 << 1));

#pragma unroll
            for (int nt = 0; nt < 2; nt++)
#pragma unroll
                for (int mt = 0; mt < 4; mt++)
                    mma16(acc[mt][nt], a[mt][0], a[mt][1], a[mt][2], a[mt][3],
                          BH[ch][nt][0], BH[ch][nt][1]);
        }

        {
            float* sgp = sg + warp * SG_WARP;
#pragma unroll
            for (int mt = 0; mt < 4; mt++) {
                int b0 = mt * 16 + r;
#pragma unroll
                for (int nt = 0; nt < 2; nt++) {
                    int n = nt * 8 + cq * 2;
                    *(float2*)&sgp[b0 * SG_STRIDE + n] =
                        make_float2(acc[mt][nt][0], acc[mt][nt][1]);
                    *(float2*)&sgp[(b0 + 8) * SG_STRIDE + n] =
                        make_float2(acc[mt][nt][2], acc[mt][nt][3]);
                }
            }
        }
        __syncthreads();

        {
            float v[4];
#pragma unroll
            for (int g = 0; g < 4; g++) {
                int n = (g << 2) + ej;
                float s = xcur[g];
#pragma unroll
                for (int w = 0; w < 8; w++) s += sg[w * SG_WARP + eb * SG_STRIDE + n];
                v[g] = s;
            }
            float si = 1.f / (1.f + __expf(-v[0]));
            float sf = 1.f / (1.f + __expf(-v[1]));
            float tg = tanhf(v[2]);
            float so = 1.f / (1.f + __expf(-v[3]));
            c_reg = sf * c_reg + si * tg;
            float hn = so * tanhf(c_reg);

            g_hbufh[(t + 1) & 1][(colj << 6) + eb] = __float2half_rn(hn);

            if (t == T_ - 1) {
                out[eb * H_ + colj]           = c_reg;   // c_fin
                out[B_ * H_ + eb * H_ + colj] = hn;      // h_fin
            }
        }

#pragma unroll
        for (int gg = 0; gg < 4; gg++) xcur[gg] = xnext[gg];

        __syncthreads();
        {
            unsigned tgt = base + 2 + (unsigned)t;
            if (tid == 0) st_rel(&g_flags[cta * 32], tgt);
            if (tid < NCTA)
                while ((int)(ld_acq(&g_flags[tid * 32]) - tgt) < 0) {}
            __syncthreads();
        }
    }
}

// ---------------------------------------------------------------------------
extern "C" void kernel_launch(void* const* d_in, const int* in_sizes, int n_in,
                              void* d_out, int out_size)
{
    const float* inputs = (const float*)d_in[0];  // [B, T, F]
    const float* Wx     = (const float*)d_in[1];  // [F, 4H]
    const float* Wh     = (const float*)d_in[2];  // [H, 4H]
    const float* bias   = (const float*)d_in[3];  // [4H]
    float* out = (float*)d_out;                   // [2, B, H] = (c_fin, h_fin)

    (void)in_sizes; (void)n_in; (void)out_size;

    conv_a<<<8192, 256>>>(inputs);
    conv_b<<<4096, 256>>>(Wx);

    cudaFuncSetAttribute(fused_kernel, cudaFuncAttributeMaxDynamicSharedMemorySize, FSMEM);
    fused_kernel<<<NCTA + GCTA, 256, FSMEM>>>(Wh, bias, out);
}